// round 6
// baseline (speedup 1.0000x reference)
#include <cuda_runtime.h>
#include <cstdint>

typedef unsigned long long u64;

#define BATCH 2
#define HH 96
#define WW 96
#define CC 128
#define KD 64
#define OD 128
#define NPIX (BATCH * HH * WW)   // 18432

__device__ float g_q[NPIX * KD];
__device__ float g_k[NPIX * KD];

// ---- packed f32x2 helpers (zero-MOV discipline: pack only at staging) ----
__device__ __forceinline__ u64 pack2(float lo, float hi) {
    u64 r; asm("mov.b64 %0, {%1, %2};" : "=l"(r) : "f"(lo), "f"(hi)); return r;
}
__device__ __forceinline__ void fma2(u64& d, u64 a, u64 b) {
    asm("fma.rn.f32x2 %0, %1, %2, %0;" : "+l"(d) : "l"(a), "l"(b));
}
__device__ __forceinline__ float hsum2(u64 v) {
    float lo, hi; asm("mov.b64 {%0, %1}, %2;" : "=f"(lo), "=f"(hi) : "l"(v));
    return lo + hi;
}
__device__ __forceinline__ void lds2(u64& a, u64& b, const void* p) {
    unsigned ad = (unsigned)__cvta_generic_to_shared(p);
    asm("ld.shared.v2.b64 {%0, %1}, [%2];" : "=l"(a), "=l"(b) : "r"(ad));
}
__device__ __forceinline__ u64 lds1(const void* p) {
    unsigned ad = (unsigned)__cvta_generic_to_shared(p);
    u64 r; asm("ld.shared.b64 %0, [%1];" : "=l"(r) : "r"(ad)); return r;
}
__device__ __forceinline__ void sts2(void* p, u64 a, u64 b) {
    unsigned ad = (unsigned)__cvta_generic_to_shared(p);
    asm volatile("st.shared.v2.b64 [%0], {%1, %2};" :: "r"(ad), "l"(a), "l"(b));
}
__device__ __forceinline__ void sts1(void* p, u64 a) {
    unsigned ad = (unsigned)__cvta_generic_to_shared(p);
    asm volatile("st.shared.b64 [%0], %1;" :: "r"(ad), "l"(a));
}
__device__ __forceinline__ void cpasync16(float* dst, const float* src, int sz) {
    unsigned daddr = (unsigned)__cvta_generic_to_shared(dst);
    asm volatile("cp.async.cg.shared.global [%0], [%1], 16, %2;"
                 :: "r"(daddr), "l"(src), "r"(sz));
}

// ---------------------------------------------------------------------------
// q/k projection: C[M,64] = A[M,128] @ W[128,64] + bias.
// 512 threads, BM=128, 4x4 per-thread tile, FFMA2 paired over k, W staged
// pair-major-over-k in smem (zero packing in inner loop). 2 CTAs/SM.
// ---------------------------------------------------------------------------
#define ASP 132

__global__ __launch_bounds__(512, 2) void gemm_qk_kernel(
    const float* __restrict__ Q,  const float* __restrict__ K,
    const float* __restrict__ Wq, const float* __restrict__ Wk,
    const float* __restrict__ bq, const float* __restrict__ bk,
    float* __restrict__ qout,     float* __restrict__ kout)
{
    extern __shared__ float sm[];
    float* As  = sm;                                    // [128][132]
    u64*   wpk = (u64*)(sm + 128 * ASP);                // [64 kb][64 n]

    const bool isK = (blockIdx.y != 0);
    const float* A    = isK ? K  : Q;
    const float* W    = isK ? Wk : Wq;
    const float* bias = isK ? bk : bq;
    float*       C    = isK ? kout : qout;

    const int m0 = blockIdx.x * 128;
    const int t  = threadIdx.x;

    // Stage A (coalesced float4, conflict-free)
    for (int i = t; i < 4096; i += 512) {
        int r = i >> 5, c4 = i & 31;
        float4 v = *reinterpret_cast<const float4*>(A + (size_t)(m0 + r) * 128 + c4 * 4);
        *reinterpret_cast<float4*>(As + r * ASP + c4 * 4) = v;
    }
    // Stage W pair-major over k: wpk[kb][n] = {W[2kb][n], W[2kb+1][n]}
    for (int it = t; it < 1024; it += 512) {
        int kb = it >> 4, n4 = (it & 15) * 4;
        float4 r0 = *reinterpret_cast<const float4*>(W + (2 * kb)     * 64 + n4);
        float4 r1 = *reinterpret_cast<const float4*>(W + (2 * kb + 1) * 64 + n4);
        sts2(wpk + kb * 64 + n4,     pack2(r0.x, r1.x), pack2(r0.y, r1.y));
        sts2(wpk + kb * 64 + n4 + 2, pack2(r0.z, r1.z), pack2(r0.w, r1.w));
    }
    __syncthreads();

    const int ty = t >> 4, tx = t & 15;
    const int row0 = ty * 4, col0 = tx * 4;

    u64 acc[4][4];
#pragma unroll
    for (int i = 0; i < 4; i++)
#pragma unroll
        for (int j = 0; j < 4; j++) acc[i][j] = 0ull;

#pragma unroll 4
    for (int kb = 0; kb < 64; kb++) {
        u64 a2[4];
#pragma unroll
        for (int i = 0; i < 4; i++) a2[i] = lds1(As + (row0 + i) * ASP + kb * 2);
        u64 w0, w1, w2, w3;
        lds2(w0, w1, wpk + kb * 64 + col0);
        lds2(w2, w3, wpk + kb * 64 + col0 + 2);
#pragma unroll
        for (int i = 0; i < 4; i++) {
            fma2(acc[i][0], a2[i], w0);
            fma2(acc[i][1], a2[i], w1);
            fma2(acc[i][2], a2[i], w2);
            fma2(acc[i][3], a2[i], w3);
        }
    }

    float b0 = bias[col0], b1 = bias[col0 + 1], b2 = bias[col0 + 2], b3 = bias[col0 + 3];
#pragma unroll
    for (int i = 0; i < 4; i++) {
        float4 o;
        o.x = hsum2(acc[i][0]) + b0;
        o.y = hsum2(acc[i][1]) + b1;
        o.z = hsum2(acc[i][2]) + b2;
        o.w = hsum2(acc[i][3]) + b3;
        *reinterpret_cast<float4*>(C + (size_t)(m0 + row0 + i) * 64 + col0) = o;
    }
}

// ---------------------------------------------------------------------------
// Fused attention + output projection. 8x8 tile / CTA, 512 threads.
// smem: sk[196][68] | sw[64][52] | swd u64[49][64] | sv[196][132]
// Overlays: wv2s u64[64][128] over sk+sw (dead after softmax);
//           at[64][132] over sv (dead after phase 4).
// ---------------------------------------------------------------------------
#define TS 8
#define WIN 14
#define SKS 68
#define SVS 132
#define SWS 52
#define ATS 132
// float offsets
#define OFF_SK  0
#define OFF_SW  (196 * SKS)                 // 13328
#define OFF_SWD (OFF_SW + 64 * SWS)         // 16656
#define OFF_SV  (OFF_SWD + 49 * 64 * 2)     // 22928
#define SMEM_ATTN_FLOATS (OFF_SV + 196 * SVS)  // 48800 -> 195200 B

__global__ __launch_bounds__(512, 1) void attn_fused_kernel(
    const float* __restrict__ qbuf,
    const float* __restrict__ kbuf,
    const float* __restrict__ V,
    const float* __restrict__ Wv,
    const float* __restrict__ bv,
    float* __restrict__ out)
{
    extern __shared__ float sm[];
    float* sk   = sm + OFF_SK;          // [196][68]
    float* sw   = sm + OFF_SW;          // [64][52]
    u64*   swd  = (u64*)(sm + OFF_SWD); // [49][64] dup'd weights
    float* sv   = sm + OFF_SV;          // [196][132]
    u64*   wv2s = (u64*)sm;             // overlay: [64 kb][128 c]
    float* at   = sv;                   // overlay: [64][132]

    const int b   = blockIdx.z;
    const int ty0 = blockIdx.y * TS;
    const int tx0 = blockIdx.x * TS;
    const int t   = threadIdx.x;

    // ---- Phase 1: async V halo; sk load ----
    for (int i = t; i < 196 * 32; i += 512) {
        int r = i >> 5, c4 = i & 31;
        int gy = ty0 - 3 + r / WIN;
        int gx = tx0 - 3 + r % WIN;
        bool ok = (gy >= 0 && gy < HH && gx >= 0 && gx < WW);
        const float* src = V + ((size_t)(b * HH + (ok ? gy : 0)) * WW + (ok ? gx : 0)) * CC + c4 * 4;
        cpasync16(sv + r * SVS + c4 * 4, src, ok ? 16 : 0);
    }
    asm volatile("cp.async.commit_group;");

    for (int i = t; i < 196 * 16; i += 512) {
        int r = i >> 4, c4 = i & 15;
        int gy = ty0 - 3 + r / WIN;
        int gx = tx0 - 3 + r % WIN;
        float4 v = make_float4(0.f, 0.f, 0.f, 0.f);
        if (gy >= 0 && gy < HH && gx >= 0 && gx < WW)
            v = *reinterpret_cast<const float4*>(
                kbuf + ((size_t)(b * HH + gy) * WW + gx) * KD + c4 * 4);
        *reinterpret_cast<float4*>(sk + r * SKS + c4 * 4) = v;
    }
    __syncthreads();

    // ---- Phase 2: scores. thread = (p, chh 0/1 x ng 0..3) ----
    // CONVERGENCE: all threads run all 13 iterations; out-of-range neighbor
    // index is clamped to 48 (safe smem) and only the store is predicated.
    const int p   = t >> 3;
    const int sub = t & 7;
    const int pry = p >> 3, prx = p & 7;
    {
        const int chh = sub >> 2;    // channel half
        const int ng  = sub & 3;     // neighbor group

        // q: 32 channels direct from global (coalesced, pairs natural)
        u64 q2[16];
        {
            const ulonglong2* qp_ = reinterpret_cast<const ulonglong2*>(
                qbuf + ((size_t)(b * HH + ty0 + pry) * WW + tx0 + prx) * KD + chh * 32);
#pragma unroll
            for (int j = 0; j < 8; j++) {
                ulonglong2 v = qp_[j];
                q2[2 * j] = v.x; q2[2 * j + 1] = v.y;
            }
        }

#pragma unroll 2
        for (int ni = 0; ni < 13; ni++) {
            const int n  = ng + ni * 4;
            const int nc = (n < 49) ? n : 48;       // clamp: safe compute
            const int dy = nc / 7, dx = nc - dy * 7;
            const float* kr = sk + ((pry + dy) * WIN + prx + dx) * SKS + chh * 32;
            u64 acc0 = 0ull, acc1 = 0ull;
#pragma unroll
            for (int j = 0; j < 8; j++) {
                u64 ka, kb2;
                lds2(ka, kb2, kr + j * 4);
                fma2(acc0, q2[2 * j], ka);
                fma2(acc1, q2[2 * j + 1], kb2);
            }
            float part = hsum2(acc0) + hsum2(acc1);
            part += __shfl_xor_sync(0xffffffffu, part, 4);  // combine ch halves (uniform)
            if (chh == 0 && n < 49) {
                int gy = ty0 + pry + dy - 3, gx = tx0 + prx + dx - 3;
                bool valid = (gy >= 0 && gy < HH && gx >= 0 && gx < WW);
                sw[p * SWS + n] = valid ? part * 0.125f : -1e30f;
            }
        }
    }
    __syncthreads();

    // ---- Phase 3: prefetch Wv rows into regs; softmax -> dup'd swd ----
    float4 wr0[4], wr1[4];
#pragma unroll
    for (int r = 0; r < 4; r++) {
        int it = t + 512 * r;           // 2048 items: (kb 0..63) x (c4 0..31)
        int kb = it >> 5, c4 = (it & 31) * 4;
        wr0[r] = *reinterpret_cast<const float4*>(Wv + (size_t)(2 * kb)     * 128 + c4);
        wr1[r] = *reinterpret_cast<const float4*>(Wv + (size_t)(2 * kb + 1) * 128 + c4);
    }

    if (t < 64) {
        const float* r = sw + t * SWS;
        float m = r[0];
#pragma unroll
        for (int n = 1; n < 49; n++) m = fmaxf(m, r[n]);
        float e[49]; float sum = 0.0f;
#pragma unroll
        for (int n = 0; n < 49; n++) { e[n] = __expf(r[n] - m); sum += e[n]; }
        float inv = 1.0f / sum;
#pragma unroll
        for (int n = 0; n < 49; n++) {
            float w = e[n] * inv;
            sts1(swd + n * 64 + t, pack2(w, w));
        }
    }
    asm volatile("cp.async.wait_group 0;");
    __syncthreads();

    // ---- Phase 4: weighted V sum. thread = (p, 16 channels) ----
    const int cc0 = sub * 16;
    u64 acc4[8];
#pragma unroll
    for (int j = 0; j < 8; j++) acc4[j] = 0ull;
    {
        int n = 0;
        for (int dy = 0; dy < 7; dy++) {
            const float* svr = sv + ((pry + dy) * WIN + prx) * SVS + cc0;
#pragma unroll
            for (int dx = 0; dx < 7; dx++) {
                u64 w = swd[n * 64 + p];                 // broadcast (8 subs same p)
                const float* vr = svr + dx * SVS;
#pragma unroll
                for (int j = 0; j < 4; j++) {
                    u64 va, vb;
                    lds2(va, vb, vr + j * 4);
                    fma2(acc4[2 * j],     w, va);
                    fma2(acc4[2 * j + 1], w, vb);
                }
                n++;
            }
        }
    }
    __syncthreads();   // sv reads + sw/sk lifetimes end

    // ---- Phase 5: store wv pair-major + attn output to smem ----
#pragma unroll
    for (int r = 0; r < 4; r++) {
        int it = t + 512 * r;
        int kb = it >> 5, c4 = (it & 31) * 4;
        sts2(wv2s + kb * 128 + c4,     pack2(wr0[r].x, wr1[r].x), pack2(wr0[r].y, wr1[r].y));
        sts2(wv2s + kb * 128 + c4 + 2, pack2(wr0[r].z, wr1[r].z), pack2(wr0[r].w, wr1[r].w));
    }
#pragma unroll
    for (int j = 0; j < 4; j++)
        sts2(at + p * ATS + cc0 + j * 4, acc4[2 * j], acc4[2 * j + 1]);
    __syncthreads();

    // ---- Phase 6: out = relu(at @ Wv + bv). thread = (4 px, 4 cols) ----
    {
        const int p0 = (t >> 5) * 4;
        const int c0 = (t & 31) * 4;

        u64 acc[4][4];
#pragma unroll
        for (int i = 0; i < 4; i++)
#pragma unroll
            for (int j = 0; j < 4; j++) acc[i][j] = 0ull;

#pragma unroll 4
        for (int kb = 0; kb < 64; kb++) {
            u64 a2[4];
#pragma unroll
            for (int i = 0; i < 4; i++) a2[i] = lds1(at + (p0 + i) * ATS + kb * 2);
            u64 w0, w1, w2, w3;
            lds2(w0, w1, wv2s + kb * 128 + c0);
            lds2(w2, w3, wv2s + kb * 128 + c0 + 2);
#pragma unroll
            for (int i = 0; i < 4; i++) {
                fma2(acc[i][0], a2[i], w0);
                fma2(acc[i][1], a2[i], w1);
                fma2(acc[i][2], a2[i], w2);
                fma2(acc[i][3], a2[i], w3);
            }
        }

        float b0 = bv[c0], b1 = bv[c0 + 1], b2 = bv[c0 + 2], b3 = bv[c0 + 3];
#pragma unroll
        for (int i = 0; i < 4; i++) {
            int pp = p0 + i;
            int py = ty0 + (pp >> 3), px = tx0 + (pp & 7);
            float4 o;
            o.x = fmaxf(hsum2(acc[i][0]) + b0, 0.0f);
            o.y = fmaxf(hsum2(acc[i][1]) + b1, 0.0f);
            o.z = fmaxf(hsum2(acc[i][2]) + b2, 0.0f);
            o.w = fmaxf(hsum2(acc[i][3]) + b3, 0.0f);
            *reinterpret_cast<float4*>(
                out + ((size_t)(b * HH + py) * WW + px) * CC + c0) = o;
        }
    }
}

// ---------------------------------------------------------------------------
extern "C" void kernel_launch(void* const* d_in, const int* in_sizes, int n_in,
                              void* d_out, int out_size)
{
    const float* Q  = (const float*)d_in[0];
    const float* K  = (const float*)d_in[1];
    const float* V  = (const float*)d_in[2];
    const float* Wq = (const float*)d_in[3];
    const float* bq = (const float*)d_in[4];
    const float* Wk = (const float*)d_in[5];
    const float* bk = (const float*)d_in[6];
    const float* Wv = (const float*)d_in[7];
    const float* bv = (const float*)d_in[8];
    float* out = (float*)d_out;

    float *qp, *kp;
    cudaGetSymbolAddress((void**)&qp, g_q);
    cudaGetSymbolAddress((void**)&kp, g_k);

    const int smem_qk   = (128 * ASP) * 4 + 64 * 64 * 8;   // 100,352 B
    const int smem_attn = SMEM_ATTN_FLOATS * 4;            // 195,200 B

    cudaFuncSetAttribute((const void*)gemm_qk_kernel,
                         cudaFuncAttributeMaxDynamicSharedMemorySize, smem_qk);
    cudaFuncSetAttribute((const void*)attn_fused_kernel,
                         cudaFuncAttributeMaxDynamicSharedMemorySize, smem_attn);

    // q/k projections: 288 CTAs, 2/SM, single wave
    gemm_qk_kernel<<<dim3(NPIX / 128, 2), 512, smem_qk>>>(Q, K, Wq, Wk, bq, bk, qp, kp);

    // fused attention + output projection
    dim3 agrid(WW / TS, HH / TS, BATCH);  // (12,12,2)
    attn_fused_kernel<<<agrid, 512, smem_attn>>>(qp, kp, V, Wv, bv, out);
}

// round 7
// speedup vs baseline: 1.2691x; 1.2691x over previous
#include <cuda_runtime.h>
#include <cstdint>

typedef unsigned long long u64;

#define BATCH 2
#define HH 96
#define WW 96
#define CC 128
#define KD 64
#define NPIX (BATCH * HH * WW)   // 18432

// Scratch (allocation-free rule)
__device__ float g_q[NPIX * KD];
__device__ float g_k[NPIX * KD];
__device__ u64   g_wq2[64 * 64];    // [kb][n]  {Wq[2kb][n], Wq[2kb+1][n]}
__device__ u64   g_wk2[64 * 64];
__device__ u64   g_wv2[64 * 128];   // [kb][c]

// ---- packed f32x2 helpers ----
__device__ __forceinline__ u64 pack2(float lo, float hi) {
    u64 r; asm("mov.b64 %0, {%1, %2};" : "=l"(r) : "f"(lo), "f"(hi)); return r;
}
__device__ __forceinline__ u64 dup2(float v) { return pack2(v, v); }
__device__ __forceinline__ void fma2(u64& d, u64 a, u64 b) {
    asm("fma.rn.f32x2 %0, %1, %2, %0;" : "+l"(d) : "l"(a), "l"(b));
}
__device__ __forceinline__ float hsum2(u64 v) {
    float lo, hi; asm("mov.b64 {%0, %1}, %2;" : "=f"(lo), "=f"(hi) : "l"(v));
    return lo + hi;
}
__device__ __forceinline__ void lds2(u64& a, u64& b, const void* p) {   // 16B aligned
    unsigned ad = (unsigned)__cvta_generic_to_shared(p);
    asm("ld.shared.v2.b64 {%0, %1}, [%2];" : "=l"(a), "=l"(b) : "r"(ad));
}
__device__ __forceinline__ u64 lds1(const void* p) {                    // 8B aligned
    unsigned ad = (unsigned)__cvta_generic_to_shared(p);
    u64 r; asm("ld.shared.b64 %0, [%1];" : "=l"(r) : "r"(ad)); return r;
}
__device__ __forceinline__ void sts2(void* p, u64 a, u64 b) {
    unsigned ad = (unsigned)__cvta_generic_to_shared(p);
    asm volatile("st.shared.v2.b64 [%0], {%1, %2};" :: "r"(ad), "l"(a), "l"(b));
}
__device__ __forceinline__ void cpasync16(float* dst, const float* src, int sz) {
    unsigned daddr = (unsigned)__cvta_generic_to_shared(dst);
    asm volatile("cp.async.cg.shared.global [%0], [%1], 16, %2;"
                 :: "r"(daddr), "l"(src), "r"(sz));
}

// ---------------------------------------------------------------------------
// Prep: pack weights pair-major over k (runs every launch; deterministic).
// ---------------------------------------------------------------------------
__global__ __launch_bounds__(256) void prep_kernel(
    const float* __restrict__ Wq, const float* __restrict__ Wk,
    const float* __restrict__ Wv)
{
    int i = blockIdx.x * 256 + threadIdx.x;    // 0..8191
    int kb = i >> 7, c = i & 127;
    g_wv2[i] = pack2(Wv[(2 * kb) * 128 + c], Wv[(2 * kb + 1) * 128 + c]);
    if (i < 4096) {
        int kq = i >> 6, cq = i & 63;
        g_wq2[i] = pack2(Wq[(2 * kq) * 64 + cq], Wq[(2 * kq + 1) * 64 + cq]);
        g_wk2[i] = pack2(Wk[(2 * kq) * 64 + cq], Wk[(2 * kq + 1) * 64 + cq]);
    }
}

// ---------------------------------------------------------------------------
// q/k projection: C[M,64] = A[M,128] @ W + bias. BM=128, 256 threads.
// 8x4 per-thread tile; a-pairs via lds1 (broadcast); w-pairs via LDG.128 (L1).
// ---------------------------------------------------------------------------
#define ASP 132

__global__ __launch_bounds__(256) void gemm_qk_kernel(
    const float* __restrict__ Q,   const float* __restrict__ K,
    const u64*   __restrict__ wq2, const u64*   __restrict__ wk2,
    const float* __restrict__ bq,  const float* __restrict__ bk,
    float* __restrict__ qout,      float* __restrict__ kout)
{
    extern __shared__ float As[];   // [128][132]

    const bool isK = (blockIdx.y != 0);
    const float* A    = isK ? K    : Q;
    const u64*   W2   = isK ? wk2  : wq2;
    const float* bias = isK ? bk   : bq;
    float*       C    = isK ? kout : qout;

    const int m0 = blockIdx.x * 128;
    const int t  = threadIdx.x;

    for (int i = t; i < 4096; i += 256) {
        int r = i >> 5, c4 = i & 31;
        float4 v = *reinterpret_cast<const float4*>(A + (size_t)(m0 + r) * 128 + c4 * 4);
        *reinterpret_cast<float4*>(As + r * ASP + c4 * 4) = v;
    }
    __syncthreads();

    const int ty = t >> 4, tx = t & 15;
    const int row0 = ty * 8, col0 = tx * 4;

    u64 acc[8][4];
#pragma unroll
    for (int i = 0; i < 8; i++)
#pragma unroll
        for (int j = 0; j < 4; j++) acc[i][j] = 0ull;

#pragma unroll 4
    for (int kb = 0; kb < 64; kb++) {
        u64 a2[8];
#pragma unroll
        for (int i = 0; i < 8; i++) a2[i] = lds1(As + (row0 + i) * ASP + kb * 2);
        ulonglong2 wa = *reinterpret_cast<const ulonglong2*>(W2 + kb * 64 + col0);
        ulonglong2 wb = *reinterpret_cast<const ulonglong2*>(W2 + kb * 64 + col0 + 2);
#pragma unroll
        for (int i = 0; i < 8; i++) {
            fma2(acc[i][0], a2[i], wa.x);
            fma2(acc[i][1], a2[i], wa.y);
            fma2(acc[i][2], a2[i], wb.x);
            fma2(acc[i][3], a2[i], wb.y);
        }
    }

    float b0 = bias[col0], b1 = bias[col0 + 1], b2 = bias[col0 + 2], b3 = bias[col0 + 3];
#pragma unroll
    for (int i = 0; i < 8; i++) {
        float4 o;
        o.x = hsum2(acc[i][0]) + b0;
        o.y = hsum2(acc[i][1]) + b1;
        o.z = hsum2(acc[i][2]) + b2;
        o.w = hsum2(acc[i][3]) + b3;
        *reinterpret_cast<float4*>(C + (size_t)(m0 + row0 + i) * 64 + col0) = o;
    }
}

// ---------------------------------------------------------------------------
// Fused attention + output projection. 8x4 pixel tile (32 px), 256 threads.
// smem regions (floats):
//   X [0, 9520):        sk[140][68]  (ph1-2)  /  sv1[140][68] ch64-127 (ph3-4b)
//   Z [9520, 11088):    sw[32][49]
//   Y [11088, 20608):   sv0[140][68] ch0-63 (ph1-4a) / at[32][132] (ph5-6)
// Total 20608 floats = 82,432 B -> 2 CTAs/SM.
// ---------------------------------------------------------------------------
#define TSY 4
#define TSX 8
#define WINX 14
#define NH 140           // 10 * 14 halo positions
#define SKS 68
#define SWS 49
#define ATS 132
#define OFF_X 0
#define OFF_Z (NH * SKS)            // 9520
#define OFF_Y (OFF_Z + 32 * SWS)    // 11088
#define SM_FLOATS (OFF_Y + NH * SKS)  // 20608

__global__ __launch_bounds__(256) void attn_fused_kernel(
    const float* __restrict__ qbuf,
    const float* __restrict__ kbuf,
    const float* __restrict__ V,
    const u64*   __restrict__ wv2,
    const float* __restrict__ bv,
    float* __restrict__ out)
{
    extern __shared__ float sm[];
    float* smX = sm + OFF_X;
    float* sw  = sm + OFF_Z;
    float* smY = sm + OFF_Y;

    const int b   = blockIdx.z;
    const int ty0 = blockIdx.y * TSY;
    const int tx0 = blockIdx.x * TSX;
    const int t   = threadIdx.x;

    const int p   = t >> 3;        // pixel 0..31
    const int sub = t & 7;         // 0..7
    const int pry = p >> 3, prx = p & 7;   // 4 rows x 8 cols

    // ---- Phase 1: cp.async sv0 (ch 0-63) into Y; LDG/STS k halo into X ----
    for (int i = t; i < NH * 16; i += 256) {
        int r = i >> 4, c4 = i & 15;
        int gy = ty0 - 3 + r / WINX;
        int gx = tx0 - 3 + r % WINX;
        bool ok = (gy >= 0 && gy < HH && gx >= 0 && gx < WW);
        const float* src = V + ((size_t)(b * HH + (ok ? gy : 0)) * WW + (ok ? gx : 0)) * CC + c4 * 4;
        cpasync16(smY + r * SKS + c4 * 4, src, ok ? 16 : 0);
    }
    asm volatile("cp.async.commit_group;");   // group A = sv0

    for (int i = t; i < NH * 16; i += 256) {
        int r = i >> 4, c4 = i & 15;
        int gy = ty0 - 3 + r / WINX;
        int gx = tx0 - 3 + r % WINX;
        float4 v = make_float4(0.f, 0.f, 0.f, 0.f);
        if (gy >= 0 && gy < HH && gx >= 0 && gx < WW)
            v = *reinterpret_cast<const float4*>(
                kbuf + ((size_t)(b * HH + gy) * WW + gx) * KD + c4 * 4);
        *reinterpret_cast<float4*>(smX + r * SKS + c4 * 4) = v;
    }
    __syncthreads();

    // ---- Phase 2: scores. thread=(p, sub -> 8 channels), all 49 neighbors ----
    {
        u64 q2[4];
        {
            const float* qp_ = qbuf +
                ((size_t)(b * HH + ty0 + pry) * WW + tx0 + prx) * KD + sub * 8;
            ulonglong2 v0 = *reinterpret_cast<const ulonglong2*>(qp_);
            ulonglong2 v1 = *reinterpret_cast<const ulonglong2*>(qp_ + 4);
            q2[0] = v0.x; q2[1] = v0.y; q2[2] = v1.x; q2[3] = v1.y;
        }

        for (int dy = 0; dy < 7; dy++) {
            const int gy = ty0 + pry + dy - 3;
#pragma unroll
            for (int dx = 0; dx < 7; dx++) {
                const int gx = tx0 + prx + dx - 3;
                const float* kr = smX + ((pry + dy) * WINX + prx + dx) * SKS + sub * 8;
                u64 ka, kb2, kc, kd;
                lds2(ka, kb2, kr);
                lds2(kc, kd, kr + 4);
                u64 a0 = 0ull, a1 = 0ull;
                fma2(a0, q2[0], ka);
                fma2(a1, q2[1], kb2);
                fma2(a0, q2[2], kc);
                fma2(a1, q2[3], kd);
                float part = hsum2(a0) + hsum2(a1);
                part += __shfl_xor_sync(0xffffffffu, part, 1);
                part += __shfl_xor_sync(0xffffffffu, part, 2);
                part += __shfl_xor_sync(0xffffffffu, part, 4);
                if (sub == 0) {
                    bool valid = (gy >= 0 && gy < HH && gx >= 0 && gx < WW);
                    sw[p * SWS + dy * 7 + dx] = valid ? part * 0.125f : -1e30f;
                }
            }
        }
    }
    __syncthreads();   // sk dead -> X reusable

    // ---- Phase 3: cp.async sv1 (ch 64-127) into X; softmax in sw ----
    for (int i = t; i < NH * 16; i += 256) {
        int r = i >> 4, c4 = i & 15;
        int gy = ty0 - 3 + r / WINX;
        int gx = tx0 - 3 + r % WINX;
        bool ok = (gy >= 0 && gy < HH && gx >= 0 && gx < WW);
        const float* src = V + ((size_t)(b * HH + (ok ? gy : 0)) * WW + (ok ? gx : 0)) * CC + 64 + c4 * 4;
        cpasync16(smX + r * SKS + c4 * 4, src, ok ? 16 : 0);
    }
    asm volatile("cp.async.commit_group;");   // group B = sv1

    if (t < 32) {
        float* r = sw + t * SWS;
        float m = r[0];
#pragma unroll
        for (int n = 1; n < 49; n++) m = fmaxf(m, r[n]);
        float e[49]; float sum = 0.0f;
#pragma unroll
        for (int n = 0; n < 49; n++) { e[n] = __expf(r[n] - m); sum += e[n]; }
        float inv = 1.0f / sum;
#pragma unroll
        for (int n = 0; n < 49; n++) r[n] = e[n] * inv;
    }
    asm volatile("cp.async.wait_group 1;");   // sv0 ready
    __syncthreads();                          // weights final

    // ---- Phase 4a: AV ch 0-63 (reads Y). thread=(p, sub -> 8 ch) ----
    u64 accA[4], accB[4];
#pragma unroll
    for (int j = 0; j < 4; j++) { accA[j] = 0ull; accB[j] = 0ull; }

    {
        const float* wr = sw + p * SWS;
        int n = 0;
        for (int dy = 0; dy < 7; dy++) {
            const float* base = smY + ((pry + dy) * WINX + prx) * SKS + sub * 8;
#pragma unroll
            for (int dx = 0; dx < 7; dx++) {
                u64 w2 = dup2(wr[n]);
                const float* vr = base + dx * SKS;
                u64 va, vb, vc, vd;
                lds2(va, vb, vr);
                lds2(vc, vd, vr + 4);
                fma2(accA[0], w2, va);
                fma2(accA[1], w2, vb);
                fma2(accA[2], w2, vc);
                fma2(accA[3], w2, vd);
                n++;
            }
        }
    }
    asm volatile("cp.async.wait_group 0;");   // sv1 ready
    __syncthreads();

    // ---- Phase 4b: AV ch 64-127 (reads X) ----
    {
        const float* wr = sw + p * SWS;
        int n = 0;
        for (int dy = 0; dy < 7; dy++) {
            const float* base = smX + ((pry + dy) * WINX + prx) * SKS + sub * 8;
#pragma unroll
            for (int dx = 0; dx < 7; dx++) {
                u64 w2 = dup2(wr[n]);
                const float* vr = base + dx * SKS;
                u64 va, vb, vc, vd;
                lds2(va, vb, vr);
                lds2(vc, vd, vr + 4);
                fma2(accB[0], w2, va);
                fma2(accB[1], w2, vb);
                fma2(accB[2], w2, vc);
                fma2(accB[3], w2, vd);
                n++;
            }
        }
    }
    __syncthreads();   // all sv0/sv1 reads done -> Y reusable

    // ---- Phase 5: attention output -> at (overlays Y) ----
    {
        float* ar = smY + p * ATS;   // at[32][132]
        sts2(ar + sub * 8,      accA[0], accA[1]);
        sts2(ar + sub * 8 + 4,  accA[2], accA[3]);
        sts2(ar + 64 + sub * 8,     accB[0], accB[1]);
        sts2(ar + 64 + sub * 8 + 4, accB[2], accB[3]);
    }
    __syncthreads();

    // ---- Phase 6: out = relu(at @ Wv + bv). thread=(4 px, 4 cols) ----
    {
        const int p0 = (t >> 5) * 4;       // warp-uniform
        const int c0 = (t & 31) * 4;
        const float* at = smY;

        u64 acc[4][4];
#pragma unroll
        for (int i = 0; i < 4; i++)
#pragma unroll
            for (int j = 0; j < 4; j++) acc[i][j] = 0ull;

#pragma unroll 4
        for (int kb = 0; kb < 64; kb++) {
            u64 a2[4];
#pragma unroll
            for (int i = 0; i < 4; i++) a2[i] = lds1(at + (p0 + i) * ATS + kb * 2);
            ulonglong2 wa = *reinterpret_cast<const ulonglong2*>(wv2 + kb * 128 + c0);
            ulonglong2 wb = *reinterpret_cast<const ulonglong2*>(wv2 + kb * 128 + c0 + 2);
#pragma unroll
            for (int i = 0; i < 4; i++) {
                fma2(acc[i][0], a2[i], wa.x);
                fma2(acc[i][1], a2[i], wa.y);
                fma2(acc[i][2], a2[i], wb.x);
                fma2(acc[i][3], a2[i], wb.y);
            }
        }

        float b0 = bv[c0], b1 = bv[c0 + 1], b2 = bv[c0 + 2], b3 = bv[c0 + 3];
#pragma unroll
        for (int i = 0; i < 4; i++) {
            int pp = p0 + i;
            int py = ty0 + (pp >> 3), px = tx0 + (pp & 7);
            float4 o;
            o.x = fmaxf(hsum2(acc[i][0]) + b0, 0.0f);
            o.y = fmaxf(hsum2(acc[i][1]) + b1, 0.0f);
            o.z = fmaxf(hsum2(acc[i][2]) + b2, 0.0f);
            o.w = fmaxf(hsum2(acc[i][3]) + b3, 0.0f);
            *reinterpret_cast<float4*>(
                out + ((size_t)(b * HH + py) * WW + px) * CC + c0) = o;
        }
    }
}

// ---------------------------------------------------------------------------
extern "C" void kernel_launch(void* const* d_in, const int* in_sizes, int n_in,
                              void* d_out, int out_size)
{
    const float* Q  = (const float*)d_in[0];
    const float* K  = (const float*)d_in[1];
    const float* V  = (const float*)d_in[2];
    const float* Wq = (const float*)d_in[3];
    const float* bq = (const float*)d_in[4];
    const float* Wk = (const float*)d_in[5];
    const float* bk = (const float*)d_in[6];
    const float* Wv = (const float*)d_in[7];
    const float* bv = (const float*)d_in[8];
    float* out = (float*)d_out;

    float *qp, *kp;
    u64 *wq2p, *wk2p, *wv2p;
    cudaGetSymbolAddress((void**)&qp,   g_q);
    cudaGetSymbolAddress((void**)&kp,   g_k);
    cudaGetSymbolAddress((void**)&wq2p, g_wq2);
    cudaGetSymbolAddress((void**)&wk2p, g_wk2);
    cudaGetSymbolAddress((void**)&wv2p, g_wv2);

    const int smem_qk   = 128 * ASP * 4;       // 67,584 B
    const int smem_attn = SM_FLOATS * 4;       // 82,432 B

    cudaFuncSetAttribute((const void*)gemm_qk_kernel,
                         cudaFuncAttributeMaxDynamicSharedMemorySize, smem_qk);
    cudaFuncSetAttribute((const void*)attn_fused_kernel,
                         cudaFuncAttributeMaxDynamicSharedMemorySize, smem_attn);

    // 1) pack weights pair-major over k
    prep_kernel<<<32, 256>>>(Wq, Wk, Wv);

    // 2) q/k projections: 288 CTAs
    gemm_qk_kernel<<<dim3(NPIX / 128, 2), 256, smem_qk>>>(
        Q, K, wq2p, wk2p, bq, bk, qp, kp);

    // 3) fused attention + output projection: 12 x 24 x 2 = 576 CTAs, 2/SM
    dim3 agrid(WW / TSX, HH / TSY, BATCH);
    attn_fused_kernel<<<agrid, 256, smem_attn>>>(qp, kp, V, wv2p, bv, out);
}

// round 8
// speedup vs baseline: 1.7394x; 1.3705x over previous
#include <cuda_runtime.h>
#include <cstdint>

typedef unsigned long long u64;

#define BATCH 2
#define HH 96
#define WW 96
#define CC 128
#define KD 64
#define NPIX (BATCH * HH * WW)   // 18432

__device__ float g_q[NPIX * KD];
__device__ float g_k[NPIX * KD];

// ---- packed f32x2 helpers ----
__device__ __forceinline__ u64 pack2(float lo, float hi) {
    u64 r; asm("mov.b64 %0, {%1, %2};" : "=l"(r) : "f"(lo), "f"(hi)); return r;
}
__device__ __forceinline__ u64 dup2(float v) { return pack2(v, v); }
__device__ __forceinline__ void fma2(u64& d, u64 a, u64 b) {
    asm("fma.rn.f32x2 %0, %1, %2, %0;" : "+l"(d) : "l"(a), "l"(b));
}
__device__ __forceinline__ float hsum2(u64 v) {
    float lo, hi; asm("mov.b64 {%0, %1}, %2;" : "=f"(lo), "=f"(hi) : "l"(v));
    return lo + hi;
}
__device__ __forceinline__ void lds2(u64& a, u64& b, const void* p) {  // 16B aligned
    unsigned ad = (unsigned)__cvta_generic_to_shared(p);
    asm("ld.shared.v2.b64 {%0, %1}, [%2];" : "=l"(a), "=l"(b) : "r"(ad));
}
__device__ __forceinline__ u64 lds1(const void* p) {                   // 8B aligned
    unsigned ad = (unsigned)__cvta_generic_to_shared(p);
    u64 r; asm("ld.shared.b64 %0, [%1];" : "=l"(r) : "r"(ad)); return r;
}
__device__ __forceinline__ void sts2(void* p, u64 a, u64 b) {
    unsigned ad = (unsigned)__cvta_generic_to_shared(p);
    asm volatile("st.shared.v2.b64 [%0], {%1, %2};" :: "r"(ad), "l"(a), "l"(b));
}
__device__ __forceinline__ void cpasync16(float* dst, const float* src, int sz) {
    unsigned daddr = (unsigned)__cvta_generic_to_shared(dst);
    asm volatile("cp.async.cg.shared.global [%0], [%1], 16, %2;"
                 :: "r"(daddr), "l"(src), "r"(sz));
}

// ---------------------------------------------------------------------------
// q/k projection: C[M,64] = A[M,128] @ W[128,64] + bias.
// 256 threads, BM=128, thread tile 8 rows (ty+16i) x 4 cols.
// W staged as TWIN u64 pair-tables (pairs over k): tabA cols {4g,4g+1},
// tabB cols {4g+2,4g+3} -> every lds2 has 16B lane stride (conflict-free).
// Inner loop: 8 lds1 (broadcast) + 2 lds2 + 32 fma2, zero MOVs. 2 CTAs/SM.
// ---------------------------------------------------------------------------
#define ASP 132

__global__ __launch_bounds__(256, 2) void gemm_qk_kernel(
    const float* __restrict__ Q,  const float* __restrict__ K,
    const float* __restrict__ Wq, const float* __restrict__ Wk,
    const float* __restrict__ bq, const float* __restrict__ bk,
    float* __restrict__ qout,     float* __restrict__ kout)
{
    extern __shared__ float smf[];
    float* As   = smf;                         // [128][132]
    u64*   tabA = (u64*)(smf + 128 * ASP);     // [64 kb][32]
    u64*   tabB = tabA + 64 * 32;              // [64 kb][32]

    const bool isK = (blockIdx.y != 0);
    const float* A    = isK ? K    : Q;
    const float* W    = isK ? Wk   : Wq;
    const float* bias = isK ? bk   : bq;
    float*       C    = isK ? kout : qout;

    const int m0 = blockIdx.x * 128;
    const int t  = threadIdx.x;

    // Stage A tile (coalesced float4, rows 528B = conflict-free)
    for (int i = t; i < 4096; i += 256) {
        int r = i >> 5, c4 = i & 31;
        float4 v = *reinterpret_cast<const float4*>(A + (size_t)(m0 + r) * 128 + c4 * 4);
        *reinterpret_cast<float4*>(As + r * ASP + c4 * 4) = v;
    }
    // Stage W twin pair-tables: item (kb 0..63, g 0..15)
    for (int i = t; i < 1024; i += 256) {
        int kb = i >> 4, g = i & 15;
        float4 r0 = *reinterpret_cast<const float4*>(W + (size_t)(2 * kb)     * 64 + 4 * g);
        float4 r1 = *reinterpret_cast<const float4*>(W + (size_t)(2 * kb + 1) * 64 + 4 * g);
        sts2(tabA + kb * 32 + 2 * g, pack2(r0.x, r1.x), pack2(r0.y, r1.y));
        sts2(tabB + kb * 32 + 2 * g, pack2(r0.z, r1.z), pack2(r0.w, r1.w));
    }
    __syncthreads();

    const int ty = t >> 4, tx = t & 15;
    const int col0 = tx * 4;

    u64 acc[8][4];
#pragma unroll
    for (int i = 0; i < 8; i++)
#pragma unroll
        for (int j = 0; j < 4; j++) acc[i][j] = 0ull;

#pragma unroll 4
    for (int kb = 0; kb < 64; kb++) {
        u64 a2[8];
#pragma unroll
        for (int i = 0; i < 8; i++)
            a2[i] = lds1(As + (ty + 16 * i) * ASP + kb * 2);   // 2 addrs/warp, bank-distinct
        u64 w0, w1, w2, w3;
        lds2(w0, w1, tabA + kb * 32 + 2 * tx);                 // 16B lane stride
        lds2(w2, w3, tabB + kb * 32 + 2 * tx);
#pragma unroll
        for (int i = 0; i < 8; i++) {
            fma2(acc[i][0], a2[i], w0);
            fma2(acc[i][1], a2[i], w1);
            fma2(acc[i][2], a2[i], w2);
            fma2(acc[i][3], a2[i], w3);
        }
    }

    float b0 = bias[col0], b1 = bias[col0 + 1], b2 = bias[col0 + 2], b3 = bias[col0 + 3];
#pragma unroll
    for (int i = 0; i < 8; i++) {
        int row = m0 + ty + 16 * i;
        float4 o;
        o.x = hsum2(acc[i][0]) + b0;
        o.y = hsum2(acc[i][1]) + b1;
        o.z = hsum2(acc[i][2]) + b2;
        o.w = hsum2(acc[i][3]) + b3;
        *reinterpret_cast<float4*>(C + (size_t)row * 64 + col0) = o;
    }
}

// ---------------------------------------------------------------------------
// Fused attention + output projection. 8x8 pixel tile, 512 threads, 288 CTAs.
// smem (floats): sk[196][68] | sw[64][52] | sv[196][132]   (170,112 B)
// Overlays (after phase 4): twin Wv pair-tables (64KB) over sk+sw;
//                           at[64][132] over sv.
// ---------------------------------------------------------------------------
#define TS 8
#define WIN 14
#define SKS 68
#define SVS 132
#define SWS 52
#define ATS 132
#define OFF_SK 0
#define OFF_SW (196 * SKS)              // 13328
#define OFF_SV (OFF_SW + 64 * SWS)      // 16656
#define SM_FLOATS (OFF_SV + 196 * SVS)  // 42528 floats = 170,112 B

__global__ __launch_bounds__(512, 1) void attn_fused_kernel(
    const float* __restrict__ qbuf,
    const float* __restrict__ kbuf,
    const float* __restrict__ V,
    const float* __restrict__ Wv,
    const float* __restrict__ bv,
    float* __restrict__ out)
{
    extern __shared__ float sm[];
    float* sk   = sm + OFF_SK;      // [196][68]
    float* sw   = sm + OFF_SW;      // [64][52]
    float* sv   = sm + OFF_SV;      // [196][132]
    u64*   tabA = (u64*)sm;         // overlay: [64 kb][64]  (32KB)
    u64*   tabB = tabA + 64 * 64;   // overlay: [64 kb][64]  (32KB; fits in sk+sw)
    float* at   = sv;               // overlay: [64][132]

    const int b   = blockIdx.z;
    const int ty0 = blockIdx.y * TS;
    const int tx0 = blockIdx.x * TS;
    const int t   = threadIdx.x;

    const int p   = t >> 3;                 // pixel 0..63
    const int sub = t & 7;                  // 0..7
    const int pry = p >> 3, prx = p & 7;

    // ---- Phase 1: cp.async V halo -> sv; LDG k halo -> sk ----
    for (int i = t; i < 196 * 32; i += 512) {
        int r = i >> 5, c4 = i & 31;
        int gy = ty0 - 3 + r / WIN;
        int gx = tx0 - 3 + r % WIN;
        bool ok = (gy >= 0 && gy < HH && gx >= 0 && gx < WW);
        const float* src = V + ((size_t)(b * HH + (ok ? gy : 0)) * WW + (ok ? gx : 0)) * CC + c4 * 4;
        cpasync16(sv + r * SVS + c4 * 4, src, ok ? 16 : 0);
    }
    asm volatile("cp.async.commit_group;");

    for (int i = t; i < 196 * 16; i += 512) {
        int r = i >> 4, c4 = i & 15;
        int gy = ty0 - 3 + r / WIN;
        int gx = tx0 - 3 + r % WIN;
        float4 v = make_float4(0.f, 0.f, 0.f, 0.f);
        if (gy >= 0 && gy < HH && gx >= 0 && gx < WW)
            v = *reinterpret_cast<const float4*>(
                kbuf + ((size_t)(b * HH + gy) * WW + gx) * KD + c4 * 4);
        *reinterpret_cast<float4*>(sk + r * SKS + c4 * 4) = v;
    }
    __syncthreads();

    // ---- Phase 2: scores. thread = (p, chh 0/1, ng 0..3); uniform 13 iters ----
    // Channel split interleaved at 16B: chh owns float chunks j*8 + chh*4.
    {
        const int chh = sub >> 2;
        const int ng  = sub & 3;

        u64 q2[16];
        {
            const float* qp_ = qbuf + ((size_t)(b * HH + ty0 + pry) * WW + tx0 + prx) * KD;
#pragma unroll
            for (int j = 0; j < 8; j++) {
                ulonglong2 v = *reinterpret_cast<const ulonglong2*>(qp_ + j * 8 + chh * 4);
                q2[2 * j] = v.x; q2[2 * j + 1] = v.y;
            }
        }

#pragma unroll 2
        for (int ni = 0; ni < 13; ni++) {
            const int n  = ng + ni * 4;
            const int nc = (n < 49) ? n : 48;          // clamp: safe compute
            const int dy = nc / 7, dx = nc - dy * 7;
            const float* kr = sk + ((pry + dy) * WIN + prx + dx) * SKS + chh * 4;
            u64 a0 = 0ull, a1 = 0ull;
#pragma unroll
            for (int j = 0; j < 8; j++) {
                u64 ka, kb2;
                lds2(ka, kb2, kr + j * 8);             // 16B lane stride across chh
                fma2(a0, q2[2 * j], ka);
                fma2(a1, q2[2 * j + 1], kb2);
            }
            float part = hsum2(a0) + hsum2(a1);
            part += __shfl_xor_sync(0xffffffffu, part, 4);   // combine chh halves
            if (chh == 0 && n < 49) {
                int gy = ty0 + pry + dy - 3, gx = tx0 + prx + dx - 3;
                bool valid = (gy >= 0 && gy < HH && gx >= 0 && gx < WW);
                sw[p * SWS + n] = valid ? part * 0.125f : -1e30f;
            }
        }
    }
    __syncthreads();

    // ---- Phase 3: issue Wv LDGs into regs; softmax in sw ----
    float4 wr0[4], wr1[4];
#pragma unroll
    for (int r = 0; r < 4; r++) {
        int i = t + 512 * r;                 // (kb 0..63) x (g 0..31)
        int kb = i >> 5, g = i & 31;
        wr0[r] = *reinterpret_cast<const float4*>(Wv + (size_t)(2 * kb)     * 128 + 4 * g);
        wr1[r] = *reinterpret_cast<const float4*>(Wv + (size_t)(2 * kb + 1) * 128 + 4 * g);
    }

    if (t < 64) {
        float* r = sw + t * SWS;
        float m = r[0];
#pragma unroll
        for (int n = 1; n < 49; n++) m = fmaxf(m, r[n]);
        float e[49]; float sum = 0.0f;
#pragma unroll
        for (int n = 0; n < 49; n++) { e[n] = __expf(r[n] - m); sum += e[n]; }
        float inv = 1.0f / sum;
#pragma unroll
        for (int n = 0; n < 49; n++) r[n] = e[n] * inv;
    }
    asm volatile("cp.async.wait_group 0;");
    __syncthreads();

    // ---- Phase 4: AV. thread = (p, sub); sub owns 16B-interleaved chunks ----
    // channel chunks c4 = sub + 8*jj (jj 0..3) -> 16B lane stride.
    u64 acc4[8];
#pragma unroll
    for (int j = 0; j < 8; j++) acc4[j] = 0ull;
    {
        const float* wr = sw + p * SWS;
        int n = 0;
        for (int dy = 0; dy < 7; dy++) {
            const float* base0 = sv + ((pry + dy) * WIN + prx) * SVS + sub * 4;
#pragma unroll
            for (int dx = 0; dx < 7; dx++) {
                u64 w2 = dup2(wr[n]);
                const float* vr = base0 + dx * SVS;
#pragma unroll
                for (int jj = 0; jj < 4; jj++) {
                    u64 va, vb;
                    lds2(va, vb, vr + jj * 32);
                    fma2(acc4[2 * jj],     w2, va);
                    fma2(acc4[2 * jj + 1], w2, vb);
                }
                n++;
            }
        }
    }
    __syncthreads();   // sv/sw/sk lifetimes end

    // ---- Phase 5: store Wv twin tables + attention output ----
#pragma unroll
    for (int r = 0; r < 4; r++) {
        int i = t + 512 * r;
        int kb = i >> 5, g = i & 31;
        sts2(tabA + kb * 64 + 2 * g, pack2(wr0[r].x, wr1[r].x), pack2(wr0[r].y, wr1[r].y));
        sts2(tabB + kb * 64 + 2 * g, pack2(wr0[r].z, wr1[r].z), pack2(wr0[r].w, wr1[r].w));
    }
#pragma unroll
    for (int jj = 0; jj < 4; jj++)
        sts2(at + p * ATS + (sub + 8 * jj) * 4, acc4[2 * jj], acc4[2 * jj + 1]);
    __syncthreads();

    // ---- Phase 6: out = relu(at @ Wv + bv). thread = (4 px, 4 cols) ----
    {
        const int p0 = (t >> 5) * 4;        // warp-uniform -> broadcast a-loads
        const int g  = t & 31;
        const int c0 = g * 4;

        u64 acc[4][4];
#pragma unroll
        for (int i = 0; i < 4; i++)
#pragma unroll
            for (int j = 0; j < 4; j++) acc[i][j] = 0ull;

#pragma unroll 4
        for (int kb = 0; kb < 64; kb++) {
            u64 a2[4];
#pragma unroll
            for (int i = 0; i < 4; i++)
                a2[i] = lds1(at + (p0 + i) * ATS + kb * 2);    // uniform addr: broadcast
            u64 w0, w1, w2, w3;
            lds2(w0, w1, tabA + kb * 64 + 2 * g);              // 16B lane stride
            lds2(w2, w3, tabB + kb * 64 + 2 * g);
#pragma unroll
            for (int i = 0; i < 4; i++) {
                fma2(acc[i][0], a2[i], w0);
                fma2(acc[i][1], a2[i], w1);
                fma2(acc[i][2], a2[i], w2);
                fma2(acc[i][3], a2[i], w3);
            }
        }

        float b0 = bv[c0], b1 = bv[c0 + 1], b2 = bv[c0 + 2], b3 = bv[c0 + 3];
#pragma unroll
        for (int i = 0; i < 4; i++) {
            int pp = p0 + i;
            int py = ty0 + (pp >> 3), px = tx0 + (pp & 7);
            float4 o;
            o.x = fmaxf(hsum2(acc[i][0]) + b0, 0.0f);
            o.y = fmaxf(hsum2(acc[i][1]) + b1, 0.0f);
            o.z = fmaxf(hsum2(acc[i][2]) + b2, 0.0f);
            o.w = fmaxf(hsum2(acc[i][3]) + b3, 0.0f);
            *reinterpret_cast<float4*>(
                out + ((size_t)(b * HH + py) * WW + px) * CC + c0) = o;
        }
    }
}

// ---------------------------------------------------------------------------
extern "C" void kernel_launch(void* const* d_in, const int* in_sizes, int n_in,
                              void* d_out, int out_size)
{
    const float* Q  = (const float*)d_in[0];
    const float* K  = (const float*)d_in[1];
    const float* V  = (const float*)d_in[2];
    const float* Wq = (const float*)d_in[3];
    const float* bq = (const float*)d_in[4];
    const float* Wk = (const float*)d_in[5];
    const float* bk = (const float*)d_in[6];
    const float* Wv = (const float*)d_in[7];
    const float* bv = (const float*)d_in[8];
    float* out = (float*)d_out;

    float *qp, *kp;
    cudaGetSymbolAddress((void**)&qp, g_q);
    cudaGetSymbolAddress((void**)&kp, g_k);

    const int smem_qk   = 128 * ASP * 4 + 2 * 64 * 32 * 8;  // 100,352 B
    const int smem_attn = SM_FLOATS * 4;                    // 170,112 B

    cudaFuncSetAttribute((const void*)gemm_qk_kernel,
                         cudaFuncAttributeMaxDynamicSharedMemorySize, smem_qk);
    cudaFuncSetAttribute((const void*)attn_fused_kernel,
                         cudaFuncAttributeMaxDynamicSharedMemorySize, smem_attn);

    // q/k projections: 288 CTAs, 2/SM, single wave
    gemm_qk_kernel<<<dim3(NPIX / 128, 2), 256, smem_qk>>>(Q, K, Wq, Wk, bq, bk, qp, kp);

    // fused attention + output projection: 288 CTAs
    dim3 agrid(WW / TS, HH / TS, BATCH);  // (12,12,2)
    attn_fused_kernel<<<agrid, 512, smem_attn>>>(qp, kp, V, Wv, bv, out);
}